// round 9
// baseline (speedup 1.0000x reference)
#include <cuda_runtime.h>
#include <cuda_pipeline.h>
#include <cuda_bf16.h>

#define NN 8192
#define CD 128

#define BK 64
#define NITER 128
#define STAGES 5
#define STAGE_B 24576
#define OFF_AL 4096
#define OFF_BH 8192
#define OFF_BL 16384
#define SMEM_TOTAL (STAGES * STAGE_B)

#define S_A 1040384.0f

__device__ signed char g_Ah8[(size_t)NN * NN];
__device__ signed char g_Al8[(size_t)NN * NN];
__device__ signed char g_Bh8[2][(size_t)CD * NN];
__device__ signed char g_Bl8[2][(size_t)CD * NN];
__device__ float g_Y[(size_t)NN * CD];
__device__ int g_scaleBits[2];

__device__ __forceinline__ void ldsm4(unsigned& r0, unsigned& r1, unsigned& r2, unsigned& r3, unsigned addr) {
    asm volatile("ldmatrix.sync.aligned.m8n8.x4.shared.b16 {%0, %1, %2, %3}, [%4];"
                 : "=r"(r0), "=r"(r1), "=r"(r2), "=r"(r3) : "r"(addr));
}
__device__ __forceinline__ void mma_s8(int* c, unsigned a0, unsigned a1, unsigned a2, unsigned a3, unsigned b0, unsigned b1) {
    asm volatile("mma.sync.aligned.m16n8k32.row.col.s32.s8.s8.s32 {%0, %1, %2, %3}, {%4, %5, %6, %7}, {%8, %9}, {%0, %1, %2, %3};"
                 : "+r"(c[0]), "+r"(c[1]), "+r"(c[2]), "+r"(c[3])
                 : "r"(a0), "r"(a1), "r"(a2), "r"(a3), "r"(b0), "r"(b1));
}

// swizzled offset for 64-byte rows: 2 rows per 128B line, 16B unit granularity
__device__ __forceinline__ unsigned sw64(int r, int c) {
    unsigned slot = (unsigned)((((r & 1) << 2) | c) ^ ((r >> 1) & 7));
    return (unsigned)((r >> 1) << 7) + (slot << 4);
}

__device__ __forceinline__ int clamp8(int v) {
    if (v > 127) v = 127;
    if (v < -127) v = -127;
    return v;
}

__global__ __launch_bounds__(256) void reset_kernel()
{
    if (threadIdx.x < 2) g_scaleBits[threadIdx.x] = 0;
}

// quantize A to 2 int8 limbs with fixed scale (A in [0, 1/8192) by construction)
__global__ __launch_bounds__(256) void convA_kernel(const float* __restrict__ A)
{
    const float4* A4 = (const float4*)A;
    unsigned* H = (unsigned*)g_Ah8;
    unsigned* L = (unsigned*)g_Al8;
    size_t n4 = (size_t)NN * NN / 4;
    size_t stride = (size_t)gridDim.x * blockDim.x;
    size_t j = (size_t)blockIdx.x * blockDim.x + threadIdx.x;
    for (; j < n4; j += stride) {
        float4 v = A4[j];
        float s0 = v.x * S_A;
        float s1 = v.y * S_A;
        float s2 = v.z * S_A;
        float s3 = v.w * S_A;
        int h0 = clamp8(__float2int_rn(s0));
        int h1 = clamp8(__float2int_rn(s1));
        int h2 = clamp8(__float2int_rn(s2));
        int h3 = clamp8(__float2int_rn(s3));
        int l0 = clamp8(__float2int_rn((s0 - (float)h0) * 128.0f));
        int l1 = clamp8(__float2int_rn((s1 - (float)h1) * 128.0f));
        int l2 = clamp8(__float2int_rn((s2 - (float)h2) * 128.0f));
        int l3 = clamp8(__float2int_rn((s3 - (float)h3) * 128.0f));
        unsigned wh = (h0 & 255) | ((h1 & 255) << 8) | ((h2 & 255) << 16) | ((h3 & 255) << 24);
        unsigned wl = (l0 & 255) | ((l1 & 255) << 8) | ((l2 & 255) << 16) | ((l3 & 255) << 24);
        H[j] = wh;
        L[j] = wl;
    }
}

__global__ __launch_bounds__(256) void maxFG_kernel(const float* __restrict__ F,
                                                    const float* __restrict__ G)
{
    int n = NN * 64;
    int stride = gridDim.x * blockDim.x;
    float m = 0.0f;
    for (int i = blockIdx.x * blockDim.x + threadIdx.x; i < n; i += stride) {
        float a = fabsf(F[i]);
        float b = fabsf(G[i]);
        if (a > m) m = a;
        if (b > m) m = b;
    }
    for (int o = 16; o > 0; o >>= 1) {
        float t = __shfl_xor_sync(0xFFFFFFFFu, m, o);
        if (t > m) m = t;
    }
    if ((threadIdx.x & 31) == 0) atomicMax(&g_scaleBits[0], __float_as_int(m));
}

__global__ __launch_bounds__(256) void maxY_kernel()
{
    int n = NN * CD;
    int stride = gridDim.x * blockDim.x;
    float m = 0.0f;
    for (int i = blockIdx.x * blockDim.x + threadIdx.x; i < n; i += stride) {
        float a = fabsf(g_Y[i]);
        if (a > m) m = a;
    }
    for (int o = 16; o > 0; o >>= 1) {
        float t = __shfl_xor_sync(0xFFFFFFFFu, m, o);
        if (t > m) m = t;
    }
    if ((threadIdx.x & 31) == 0) atomicMax(&g_scaleBits[1], __float_as_int(m));
}

// pack layer-1 B: [F|G] -> K-major int8 limbs
__global__ __launch_bounds__(256) void packX_kernel(const float* __restrict__ F,
                                                    const float* __restrict__ G)
{
    int idx = blockIdx.x * blockDim.x + threadIdx.x;
    int col = idx >> 13;
    int row = idx & (NN - 1);
    float v;
    if (col < 64) v = F[row * 64 + col];
    else v = G[row * 64 + (col - 64)];
    float maxv = __int_as_float(g_scaleBits[0]);
    float s = 127.0f / maxv;
    float x = v * s;
    int h = clamp8(__float2int_rn(x));
    int l = clamp8(__float2int_rn((x - (float)h) * 128.0f));
    g_Bh8[0][idx] = (signed char)h;
    g_Bl8[0][idx] = (signed char)l;
}

// pack layer-2 B: g_Y -> K-major int8 limbs
__global__ __launch_bounds__(256) void packY_kernel()
{
    int idx = blockIdx.x * blockDim.x + threadIdx.x;
    int col = idx >> 13;
    int row = idx & (NN - 1);
    float v = g_Y[(size_t)row * CD + col];
    float maxv = __int_as_float(g_scaleBits[1]);
    float s = 127.0f / maxv;
    float x = v * s;
    int h = clamp8(__float2int_rn(x));
    int l = clamp8(__float2int_rn((x - (float)h) * 128.0f));
    g_Bh8[1][idx] = (signed char)h;
    g_Bl8[1][idx] = (signed char)l;
}

__device__ __forceinline__ void load_stage(char* smem, int s, int it, int tid, size_t arow0,
                                           const signed char* __restrict__ Bh,
                                           const signed char* __restrict__ Bl)
{
    char* st = smem + s * STAGE_B;
    size_t k0 = (size_t)it * BK;

    int ar = tid >> 2;
    int ac = tid & 3;
    unsigned aso = sw64(ar, ac);
    size_t aoff = (arow0 + ar) * NN + k0 + ac * 16;
    __pipeline_memcpy_async(st + aso, g_Ah8 + aoff, 16);
    __pipeline_memcpy_async(st + OFF_AL + aso, g_Al8 + aoff, 16);

    int i;
#pragma unroll
    for (i = 0; i < 2; ++i) {
        int u = tid + i * 256;
        int br = u >> 2;
        int bc = u & 3;
        unsigned bso = sw64(br, bc);
        size_t boff = (size_t)br * NN + k0 + bc * 16;
        __pipeline_memcpy_async(st + OFF_BH + bso, Bh + boff, 16);
        __pipeline_memcpy_async(st + OFF_BL + bso, Bl + boff, 16);
    }
    __pipeline_commit();
}

__global__ __launch_bounds__(256) void gemm_kernel(int layer, float* __restrict__ out)
{
    extern __shared__ char smem[];
    const int tid = threadIdx.x;
    const int lane = tid & 31;
    const int warp = tid >> 5;
    const int wm = warp & 1;
    const int wn = warp >> 1;

    unsigned sbase = (unsigned)__cvta_generic_to_shared(smem);

    const signed char* Bh = g_Bh8[layer];
    const signed char* Bl = g_Bl8[layer];

    const size_t arow0 = (size_t)blockIdx.x * 64;

    int accHH[2][4][4];
    int accX[2][4][4];
    int t, j, q;
#pragma unroll
    for (t = 0; t < 2; ++t)
#pragma unroll
        for (j = 0; j < 4; ++j)
#pragma unroll
            for (q = 0; q < 4; ++q) {
                accHH[t][j][q] = 0;
                accX[t][j][q] = 0;
            }

    load_stage(smem, 0, 0, tid, arow0, Bh, Bl);
    load_stage(smem, 1, 1, tid, arow0, Bh, Bl);
    load_stage(smem, 2, 2, tid, arow0, Bh, Bl);
    load_stage(smem, 3, 3, tid, arow0, Bh, Bl);
    load_stage(smem, 4, 4, tid, arow0, Bh, Bl);

    const int a_roff = lane & 15;
    const int a_coff = lane >> 4;
    const int b_m = lane >> 3;
    const int b_roff = ((b_m >> 1) * 8) + (lane & 7);
    const int b_coff = b_m & 1;

    for (int it = 0; it < NITER; ++it) {
        int s = it - (it / STAGES) * STAGES;
        __pipeline_wait_prior(STAGES - 1);
        __syncthreads();

        unsigned stb = sbase + s * STAGE_B;
        int ks;
#pragma unroll
        for (ks = 0; ks < 2; ++ks) {
            unsigned ah[2][4];
            unsigned al[2][4];
#pragma unroll
            for (t = 0; t < 2; ++t) {
                int row = wm * 32 + t * 16 + a_roff;
                int chunk = ks * 2 + a_coff;
                unsigned so = sw64(row, chunk);
                ldsm4(ah[t][0], ah[t][1], ah[t][2], ah[t][3], stb + so);
                ldsm4(al[t][0], al[t][1], al[t][2], al[t][3], stb + OFF_AL + so);
            }
            unsigned bh[4][2];
            unsigned bl[4][2];
            int p;
#pragma unroll
            for (p = 0; p < 2; ++p) {
                int row = wn * 32 + p * 16 + b_roff;
                int chunk = ks * 2 + b_coff;
                unsigned so = sw64(row, chunk);
                unsigned r0, r1, r2, r3;
                ldsm4(r0, r1, r2, r3, stb + OFF_BH + so);
                bh[p * 2][0] = r0;
                bh[p * 2][1] = r1;
                bh[p * 2 + 1][0] = r2;
                bh[p * 2 + 1][1] = r3;
                ldsm4(r0, r1, r2, r3, stb + OFF_BL + so);
                bl[p * 2][0] = r0;
                bl[p * 2][1] = r1;
                bl[p * 2 + 1][0] = r2;
                bl[p * 2 + 1][1] = r3;
            }
#pragma unroll
            for (t = 0; t < 2; ++t) {
#pragma unroll
                for (j = 0; j < 4; ++j) {
                    mma_s8(accHH[t][j], ah[t][0], ah[t][1], ah[t][2], ah[t][3], bh[j][0], bh[j][1]);
                    mma_s8(accX[t][j], ah[t][0], ah[t][1], ah[t][2], ah[t][3], bl[j][0], bl[j][1]);
                    mma_s8(accX[t][j], al[t][0], al[t][1], al[t][2], al[t][3], bh[j][0], bh[j][1]);
                }
            }
        }

        __syncthreads();
        if (it + STAGES < NITER) {
            load_stage(smem, s, it + STAGES, tid, arow0, Bh, Bl);
        } else {
            __pipeline_commit();
        }
    }

    float* dst = out;
    if (layer == 0) dst = (float*)g_Y;

    float maxv = __int_as_float(g_scaleBits[layer]);
    float inv = maxv / (127.0f * S_A);

    const int g = lane >> 2;
    const int tig = lane & 3;
#pragma unroll
    for (t = 0; t < 2; ++t) {
#pragma unroll
        for (j = 0; j < 4; ++j) {
            int col = wn * 32 + j * 8 + tig * 2;
            size_t row0 = arow0 + wm * 32 + t * 16 + g;
            size_t row1 = row0 + 8;
            float2 v0;
            float2 v1;
            v0.x = ((float)accHH[t][j][0] + (float)accX[t][j][0] * 0.0078125f) * inv;
            v0.y = ((float)accHH[t][j][1] + (float)accX[t][j][1] * 0.0078125f) * inv;
            v1.x = ((float)accHH[t][j][2] + (float)accX[t][j][2] * 0.0078125f) * inv;
            v1.y = ((float)accHH[t][j][3] + (float)accX[t][j][3] * 0.0078125f) * inv;
            if (col < 64) {
                v0.x = fmaxf(v0.x, 0.0f);
                v0.y = fmaxf(v0.y, 0.0f);
                v1.x = fmaxf(v1.x, 0.0f);
                v1.y = fmaxf(v1.y, 0.0f);
            }
            *reinterpret_cast<float2*>(dst + row0 * CD + col) = v0;
            *reinterpret_cast<float2*>(dst + row1 * CD + col) = v1;
        }
    }
}

extern "C" void kernel_launch(void* const* d_in, const int* in_sizes, int n_in,
                              void* d_out, int out_size)
{
    const float* A = (const float*)d_in[0];
    const float* F = (const float*)d_in[1];
    const float* G = (const float*)d_in[2];
    float* out = (float*)d_out;

    cudaFuncSetAttribute(gemm_kernel, cudaFuncAttributeMaxDynamicSharedMemorySize, SMEM_TOTAL);

    reset_kernel<<<1, 256>>>();
    convA_kernel<<<2048, 256>>>(A);
    maxFG_kernel<<<512, 256>>>(F, G);
    packX_kernel<<<(CD * NN) / 256, 256>>>(F, G);
    gemm_kernel<<<NN / 64, 256, SMEM_TOTAL>>>(0, out);
    maxY_kernel<<<512, 256>>>();
    packY_kernel<<<(CD * NN) / 256, 256>>>();
    gemm_kernel<<<NN / 64, 256, SMEM_TOTAL>>>(1, out);
}

// round 12
// speedup vs baseline: 1.3469x; 1.3469x over previous
#include <cuda_runtime.h>
#include <cuda_pipeline.h>
#include <cuda_bf16.h>

#define NN 8192
#define CD 128

#define BK 32
#define NITER 256
#define STAGES 5
#define STAGE_B 24576
#define OFF_ALO 4096
#define OFF_BHI 8192
#define OFF_BLO 16384
#define SMEM_TOTAL (STAGES * STAGE_B)

__device__ __nv_bfloat16 g_Bhi[2][(size_t)CD * NN];
__device__ __nv_bfloat16 g_Blo[2][(size_t)CD * NN];
__device__ float g_Y[(size_t)NN * CD];

__device__ __forceinline__ void ldsm4(unsigned& r0, unsigned& r1, unsigned& r2, unsigned& r3, unsigned addr) {
    asm volatile("ldmatrix.sync.aligned.m8n8.x4.shared.b16 {%0, %1, %2, %3}, [%4];"
                 : "=r"(r0), "=r"(r1), "=r"(r2), "=r"(r3) : "r"(addr));
}
__device__ __forceinline__ void mma16816(float* c, unsigned a0, unsigned a1, unsigned a2, unsigned a3, unsigned b0, unsigned b1) {
    asm volatile("mma.sync.aligned.m16n8k16.row.col.f32.bf16.bf16.f32 {%0, %1, %2, %3}, {%4, %5, %6, %7}, {%8, %9}, {%0, %1, %2, %3};"
                 : "+f"(c[0]), "+f"(c[1]), "+f"(c[2]), "+f"(c[3])
                 : "r"(a0), "r"(a1), "r"(a2), "r"(a3), "r"(b0), "r"(b1));
}

__device__ __forceinline__ unsigned sw_off(int row, int chunk) {
    return (unsigned)(row * 64 + (chunk ^ ((row >> 1) & 3)) * 16);
}

__device__ __forceinline__ void split_bf16(float v, __nv_bfloat16& h, __nv_bfloat16& l) {
    h = __float2bfloat16_rn(v);
    l = __float2bfloat16_rn(v - __bfloat162float(h));
}
__device__ __forceinline__ unsigned pack_bf2(__nv_bfloat16 a, __nv_bfloat16 b) {
    unsigned lo = (unsigned)__bfloat16_as_ushort(a);
    unsigned hi = (unsigned)__bfloat16_as_ushort(b);
    return lo | (hi << 16);
}

__global__ __launch_bounds__(256) void packX_kernel(const float* __restrict__ F,
                                                    const float* __restrict__ G)
{
    int idx = blockIdx.x * blockDim.x + threadIdx.x;
    int col = idx >> 13;
    int row = idx & (NN - 1);
    float v;
    if (col < 64) v = F[row * 64 + col];
    else v = G[row * 64 + (col - 64)];
    __nv_bfloat16 h, l;
    split_bf16(v, h, l);
    g_Bhi[0][idx] = h;
    g_Blo[0][idx] = l;
}

__global__ __launch_bounds__(256) void packY_kernel()
{
    int idx = blockIdx.x * blockDim.x + threadIdx.x;
    int col = idx >> 13;
    int row = idx & (NN - 1);
    float v = g_Y[(size_t)row * CD + col];
    __nv_bfloat16 h, l;
    split_bf16(v, h, l);
    g_Bhi[1][idx] = h;
    g_Blo[1][idx] = l;
}

// issue the two fp32 LDGs for this thread's A piece of iteration `it`
__device__ __forceinline__ void ldgA(const float* __restrict__ A, int it, int tid, size_t arow0,
                                     float4& a0, float4& a1)
{
    int arow = tid >> 2;
    int achunk = tid & 3;
    size_t off = (arow0 + arow) * NN + (size_t)it * BK + achunk * 8;
    const float4* p = (const float4*)(A + off);
    a0 = p[0];
    a1 = p[1];
}

// split the 8 fp32 values into bf16 hi/lo limbs and store to stage s
__device__ __forceinline__ void stsA(char* smem, int s, int tid, float4 a0, float4 a1)
{
    char* st = smem + s * STAGE_B;
    int arow = tid >> 2;
    int achunk = tid & 3;
    unsigned aso = sw_off(arow, achunk);
    __nv_bfloat16 h0, h1, h2, h3, h4, h5, h6, h7;
    __nv_bfloat16 l0, l1, l2, l3, l4, l5, l6, l7;
    split_bf16(a0.x, h0, l0);
    split_bf16(a0.y, h1, l1);
    split_bf16(a0.z, h2, l2);
    split_bf16(a0.w, h3, l3);
    split_bf16(a1.x, h4, l4);
    split_bf16(a1.y, h5, l5);
    split_bf16(a1.z, h6, l6);
    split_bf16(a1.w, h7, l7);
    uint4 wh;
    wh.x = pack_bf2(h0, h1);
    wh.y = pack_bf2(h2, h3);
    wh.z = pack_bf2(h4, h5);
    wh.w = pack_bf2(h6, h7);
    uint4 wl;
    wl.x = pack_bf2(l0, l1);
    wl.y = pack_bf2(l2, l3);
    wl.z = pack_bf2(l4, l5);
    wl.w = pack_bf2(l6, l7);
    *reinterpret_cast<uint4*>(st + aso) = wh;
    *reinterpret_cast<uint4*>(st + OFF_ALO + aso) = wl;
}

// B-only async stage load (one commit per call, same accounting as before)
__device__ __forceinline__ void load_stage_B(char* smem, int s, int it, int tid,
                                             const __nv_bfloat16* __restrict__ Bhi,
                                             const __nv_bfloat16* __restrict__ Blo)
{
    char* st = smem + s * STAGE_B;
    size_t k0 = (size_t)it * BK;
    int i;
#pragma unroll
    for (i = 0; i < 2; ++i) {
        int u = tid + i * 256;
        int brow = u >> 2;
        int bchunk = u & 3;
        unsigned bso = sw_off(brow, bchunk);
        size_t boff = (size_t)brow * NN + k0 + bchunk * 8;
        __pipeline_memcpy_async(st + OFF_BHI + bso, Bhi + boff, 16);
        __pipeline_memcpy_async(st + OFF_BLO + bso, Blo + boff, 16);
    }
    __pipeline_commit();
}

__global__ __launch_bounds__(256) void gemm_kernel(const float* __restrict__ A,
                                                   int layer, float* __restrict__ out)
{
    extern __shared__ char smem[];
    const int tid = threadIdx.x;
    const int lane = tid & 31;
    const int warp = tid >> 5;
    const int wm = warp & 1;
    const int wn = warp >> 1;

    unsigned sbase = (unsigned)__cvta_generic_to_shared(smem);

    const __nv_bfloat16* Bhi = g_Bhi[layer];
    const __nv_bfloat16* Blo = g_Blo[layer];

    const size_t arow0 = (size_t)blockIdx.x * 64;

    float acc[2][4][4];
    int t, j, q;
#pragma unroll
    for (t = 0; t < 2; ++t)
#pragma unroll
        for (j = 0; j < 4; ++j)
#pragma unroll
            for (q = 0; q < 4; ++q) acc[t][j][q] = 0.0f;

    // prologue: A via LDG+split+STS, B via cp.async, for stages 0..4
    {
        float4 p0[STAGES];
        float4 p1[STAGES];
        int c;
#pragma unroll
        for (c = 0; c < STAGES; ++c) ldgA(A, c, tid, arow0, p0[c], p1[c]);
#pragma unroll
        for (c = 0; c < STAGES; ++c) stsA(smem, c, tid, p0[c], p1[c]);
#pragma unroll
        for (c = 0; c < STAGES; ++c) load_stage_B(smem, c, c, tid, Bhi, Blo);
    }

    const int a_roff = lane & 15;
    const int a_coff = lane >> 4;
    const int b_m = lane >> 3;
    const int b_roff = ((b_m >> 1) * 8) + (lane & 7);
    const int b_coff = b_m & 1;

    for (int it = 0; it < NITER; ++it) {
        int s = it - (it / STAGES) * STAGES;
        __pipeline_wait_prior(STAGES - 1);
        __syncthreads();

        // prefetch A for it+STAGES now; STS happens after the bottom barrier,
        // ~1300 cycles of HMMA hide the LDG latency
        float4 a0, a1;
        if (it + STAGES < NITER) ldgA(A, it + STAGES, tid, arow0, a0, a1);

        unsigned stb = sbase + s * STAGE_B;
        int ks;
#pragma unroll
        for (ks = 0; ks < 2; ++ks) {
            unsigned ah[2][4];
            unsigned al[2][4];
#pragma unroll
            for (t = 0; t < 2; ++t) {
                int row = wm * 32 + t * 16 + a_roff;
                int chunk = ks * 2 + a_coff;
                unsigned so = sw_off(row, chunk);
                ldsm4(ah[t][0], ah[t][1], ah[t][2], ah[t][3], stb + so);
                ldsm4(al[t][0], al[t][1], al[t][2], al[t][3], stb + OFF_ALO + so);
            }
            unsigned bh[4][2];
            unsigned bl[4][2];
            int p;
#pragma unroll
            for (p = 0; p < 2; ++p) {
                int row = wn * 32 + p * 16 + b_roff;
                int chunk = ks * 2 + b_coff;
                unsigned so = sw_off(row, chunk);
                unsigned r0, r1, r2, r3;
                ldsm4(r0, r1, r2, r3, stb + OFF_BHI + so);
                bh[p * 2][0] = r0;
                bh[p * 2][1] = r1;
                bh[p * 2 + 1][0] = r2;
                bh[p * 2 + 1][1] = r3;
                ldsm4(r0, r1, r2, r3, stb + OFF_BLO + so);
                bl[p * 2][0] = r0;
                bl[p * 2][1] = r1;
                bl[p * 2 + 1][0] = r2;
                bl[p * 2 + 1][1] = r3;
            }
#pragma unroll
            for (t = 0; t < 2; ++t) {
#pragma unroll
                for (j = 0; j < 4; ++j) {
                    mma16816(acc[t][j], ah[t][0], ah[t][1], ah[t][2], ah[t][3], bh[j][0], bh[j][1]);
                    mma16816(acc[t][j], ah[t][0], ah[t][1], ah[t][2], ah[t][3], bl[j][0], bl[j][1]);
                    mma16816(acc[t][j], al[t][0], al[t][1], al[t][2], al[t][3], bh[j][0], bh[j][1]);
                }
            }
        }

        __syncthreads();
        if (it + STAGES < NITER) {
            stsA(smem, s, tid, a0, a1);
            load_stage_B(smem, s, it + STAGES, tid, Bhi, Blo);
        } else {
            __pipeline_commit();
        }
    }

    float* dst = out;
    if (layer == 0) dst = (float*)g_Y;

    const int g = lane >> 2;
    const int tig = lane & 3;
#pragma unroll
    for (t = 0; t < 2; ++t) {
#pragma unroll
        for (j = 0; j < 4; ++j) {
            int col = wn * 32 + j * 8 + tig * 2;
            size_t row0 = arow0 + wm * 32 + t * 16 + g;
            size_t row1 = row0 + 8;
            float2 v0;
            float2 v1;
            v0.x = acc[t][j][0];
            v0.y = acc[t][j][1];
            v1.x = acc[t][j][2];
            v1.y = acc[t][j][3];
            if (col < 64) {
                v0.x = fmaxf(v0.x, 0.0f);
                v0.y = fmaxf(v0.y, 0.0f);
                v1.x = fmaxf(v1.x, 0.0f);
                v1.y = fmaxf(v1.y, 0.0f);
            }
            *reinterpret_cast<float2*>(dst + row0 * CD + col) = v0;
            *reinterpret_cast<float2*>(dst + row1 * CD + col) = v1;
        }
    }
}

extern "C" void kernel_launch(void* const* d_in, const int* in_sizes, int n_in,
                              void* d_out, int out_size)
{
    const float* A = (const float*)d_in[0];
    const float* F = (const float*)d_in[1];
    const float* G = (const float*)d_in[2];
    float* out = (float*)d_out;

    cudaFuncSetAttribute(gemm_kernel, cudaFuncAttributeMaxDynamicSharedMemorySize, SMEM_TOTAL);

    packX_kernel<<<(CD * NN) / 256, 256>>>(F, G);
    gemm_kernel<<<NN / 64, 256, SMEM_TOTAL>>>(A, 0, out);
    packY_kernel<<<(CD * NN) / 256, 256>>>();
    gemm_kernel<<<NN / 64, 256, SMEM_TOTAL>>>(A, 1, out);
}

// round 14
// speedup vs baseline: 2.6133x; 1.9402x over previous
#include <cuda_runtime.h>
#include <cuda_pipeline.h>
#include <cuda_bf16.h>

#define NN 8192
#define CD 128

#define BK 32
#define NITER2 128
#define STAGES 4
#define STAGE_B 24576
#define OFF_ALO 4096
#define OFF_BHI 8192
#define OFF_BLO 16384
#define SMEM_TOTAL (STAGES * STAGE_B)

__device__ __nv_bfloat16 g_Bhi[2][(size_t)CD * NN];
__device__ __nv_bfloat16 g_Blo[2][(size_t)CD * NN];
__device__ float g_P[2][(size_t)NN * CD];

__device__ __forceinline__ void ldsm4(unsigned& r0, unsigned& r1, unsigned& r2, unsigned& r3, unsigned addr) {
    asm volatile("ldmatrix.sync.aligned.m8n8.x4.shared.b16 {%0, %1, %2, %3}, [%4];"
                 : "=r"(r0), "=r"(r1), "=r"(r2), "=r"(r3) : "r"(addr));
}
__device__ __forceinline__ void mma16816(float* c, unsigned a0, unsigned a1, unsigned a2, unsigned a3, unsigned b0, unsigned b1) {
    asm volatile("mma.sync.aligned.m16n8k16.row.col.f32.bf16.bf16.f32 {%0, %1, %2, %3}, {%4, %5, %6, %7}, {%8, %9}, {%0, %1, %2, %3};"
                 : "+f"(c[0]), "+f"(c[1]), "+f"(c[2]), "+f"(c[3])
                 : "r"(a0), "r"(a1), "r"(a2), "r"(a3), "r"(b0), "r"(b1));
}

__device__ __forceinline__ unsigned sw_off(int row, int chunk) {
    return (unsigned)(row * 64 + (chunk ^ ((row >> 1) & 3)) * 16);
}

__device__ __forceinline__ void split_bf16(float v, __nv_bfloat16& h, __nv_bfloat16& l) {
    h = __float2bfloat16_rn(v);
    l = __float2bfloat16_rn(v - __bfloat162float(h));
}
__device__ __forceinline__ unsigned pack_bf2(__nv_bfloat16 a, __nv_bfloat16 b) {
    unsigned lo = (unsigned)__bfloat16_as_ushort(a);
    unsigned hi = (unsigned)__bfloat16_as_ushort(b);
    return lo | (hi << 16);
}

__global__ __launch_bounds__(256) void packX_kernel(const float* __restrict__ F,
                                                    const float* __restrict__ G)
{
    int idx = blockIdx.x * blockDim.x + threadIdx.x;
    int col = idx >> 13;
    int row = idx & (NN - 1);
    float v;
    if (col < 64) v = F[row * 64 + col];
    else v = G[row * 64 + (col - 64)];
    __nv_bfloat16 h, l;
    split_bf16(v, h, l);
    g_Bhi[0][idx] = h;
    g_Blo[0][idx] = l;
}

// combine K-split partials of layer 1, apply ReLU on cols<64, and emit the
// layer-2 B operand (K-major bf16 limbs) directly.
__global__ __launch_bounds__(256) void combine0_kernel()
{
    int idx = blockIdx.x * blockDim.x + threadIdx.x;   // idx = col*NN + row
    int col = idx >> 13;
    int row = idx & (NN - 1);
    size_t p = (size_t)row * CD + col;
    float v = g_P[0][p] + g_P[1][p];
    if (col < 64) v = fmaxf(v, 0.0f);
    __nv_bfloat16 h, l;
    split_bf16(v, h, l);
    g_Bhi[1][idx] = h;
    g_Blo[1][idx] = l;
}

// combine K-split partials of layer 2, ReLU cols<64, write final output
__global__ __launch_bounds__(256) void combine1_kernel(float* __restrict__ out)
{
    int idx = blockIdx.x * blockDim.x + threadIdx.x;   // row-major over NN*CD
    int col = idx & (CD - 1);
    float v = g_P[0][idx] + g_P[1][idx];
    if (col < 64) v = fmaxf(v, 0.0f);
    out[idx] = v;
}

__device__ __forceinline__ void ldgA(const float* __restrict__ A, int it, int tid,
                                     size_t arow0, size_t kbase,
                                     float4& a0, float4& a1)
{
    int arow = tid >> 2;
    int achunk = tid & 3;
    size_t off = (arow0 + arow) * NN + kbase + (size_t)it * BK + achunk * 8;
    const float4* p = (const float4*)(A + off);
    a0 = p[0];
    a1 = p[1];
}

__device__ __forceinline__ void stsA(char* smem, int s, int tid, float4 a0, float4 a1)
{
    char* st = smem + s * STAGE_B;
    int arow = tid >> 2;
    int achunk = tid & 3;
    unsigned aso = sw_off(arow, achunk);
    __nv_bfloat16 h0, h1, h2, h3, h4, h5, h6, h7;
    __nv_bfloat16 l0, l1, l2, l3, l4, l5, l6, l7;
    split_bf16(a0.x, h0, l0);
    split_bf16(a0.y, h1, l1);
    split_bf16(a0.z, h2, l2);
    split_bf16(a0.w, h3, l3);
    split_bf16(a1.x, h4, l4);
    split_bf16(a1.y, h5, l5);
    split_bf16(a1.z, h6, l6);
    split_bf16(a1.w, h7, l7);
    uint4 wh;
    wh.x = pack_bf2(h0, h1);
    wh.y = pack_bf2(h2, h3);
    wh.z = pack_bf2(h4, h5);
    wh.w = pack_bf2(h6, h7);
    uint4 wl;
    wl.x = pack_bf2(l0, l1);
    wl.y = pack_bf2(l2, l3);
    wl.z = pack_bf2(l4, l5);
    wl.w = pack_bf2(l6, l7);
    *reinterpret_cast<uint4*>(st + aso) = wh;
    *reinterpret_cast<uint4*>(st + OFF_ALO + aso) = wl;
}

__device__ __forceinline__ void load_stage_B(char* smem, int s, int it, int tid, size_t kbase,
                                             const __nv_bfloat16* __restrict__ Bhi,
                                             const __nv_bfloat16* __restrict__ Blo)
{
    char* st = smem + s * STAGE_B;
    size_t k0 = kbase + (size_t)it * BK;
    int i;
#pragma unroll
    for (i = 0; i < 2; ++i) {
        int u = tid + i * 256;
        int brow = u >> 2;
        int bchunk = u & 3;
        unsigned bso = sw_off(brow, bchunk);
        size_t boff = (size_t)brow * NN + k0 + bchunk * 8;
        __pipeline_memcpy_async(st + OFF_BHI + bso, Bhi + boff, 16);
        __pipeline_memcpy_async(st + OFF_BLO + bso, Blo + boff, 16);
    }
    __pipeline_commit();
}

__global__ __launch_bounds__(256, 2) void gemm_kernel(const float* __restrict__ A, int layer)
{
    extern __shared__ char smem[];
    const int tid = threadIdx.x;
    const int lane = tid & 31;
    const int warp = tid >> 5;
    const int wm = warp & 1;
    const int wn = warp >> 1;
    const int kh = blockIdx.y;

    unsigned sbase = (unsigned)__cvta_generic_to_shared(smem);

    const __nv_bfloat16* Bhi = g_Bhi[layer];
    const __nv_bfloat16* Blo = g_Blo[layer];

    const size_t arow0 = (size_t)blockIdx.x * 64;
    const size_t kbase = (size_t)kh * (NN / 2);

    float acc[2][4][4];
    int t, j, q;
#pragma unroll
    for (t = 0; t < 2; ++t)
#pragma unroll
        for (j = 0; j < 4; ++j)
#pragma unroll
            for (q = 0; q < 4; ++q) acc[t][j][q] = 0.0f;

    // prologue: fill all 4 stages
    {
        float4 p0[STAGES];
        float4 p1[STAGES];
        int c;
#pragma unroll
        for (c = 0; c < STAGES; ++c) ldgA(A, c, tid, arow0, kbase, p0[c], p1[c]);
#pragma unroll
        for (c = 0; c < STAGES; ++c) stsA(smem, c, tid, p0[c], p1[c]);
#pragma unroll
        for (c = 0; c < STAGES; ++c) load_stage_B(smem, c, c, tid, kbase, Bhi, Blo);
    }

    const int a_roff = lane & 15;
    const int a_coff = lane >> 4;
    const int b_m = lane >> 3;
    const int b_roff = ((b_m >> 1) * 8) + (lane & 7);
    const int b_coff = b_m & 1;

    for (int it = 0; it < NITER2; ++it) {
        int s = it - (it / STAGES) * STAGES;
        __pipeline_wait_prior(STAGES - 1);
        __syncthreads();

        float4 a0, a1;
        if (it + STAGES < NITER2) ldgA(A, it + STAGES, tid, arow0, kbase, a0, a1);

        unsigned stb = sbase + s * STAGE_B;
        int ks;
#pragma unroll
        for (ks = 0; ks < 2; ++ks) {
            unsigned ah[2][4];
            unsigned al[2][4];
#pragma unroll
            for (t = 0; t < 2; ++t) {
                int row = wm * 32 + t * 16 + a_roff;
                int chunk = ks * 2 + a_coff;
                unsigned so = sw_off(row, chunk);
                ldsm4(ah[t][0], ah[t][1], ah[t][2], ah[t][3], stb + so);
                ldsm4(al[t][0], al[t][1], al[t][2], al[t][3], stb + OFF_ALO + so);
            }
            unsigned bh[4][2];
            unsigned bl[4][2];
            int p;
#pragma unroll
            for (p = 0; p < 2; ++p) {
                int row = wn * 32 + p * 16 + b_roff;
                int chunk = ks * 2 + b_coff;
                unsigned so = sw_off(row, chunk);
                unsigned r0, r1, r2, r3;
                ldsm4(r0, r1, r2, r3, stb + OFF_BHI + so);
                bh[p * 2][0] = r0;
                bh[p * 2][1] = r1;
                bh[p * 2 + 1][0] = r2;
                bh[p * 2 + 1][1] = r3;
                ldsm4(r0, r1, r2, r3, stb + OFF_BLO + so);
                bl[p * 2][0] = r0;
                bl[p * 2][1] = r1;
                bl[p * 2 + 1][0] = r2;
                bl[p * 2 + 1][1] = r3;
            }
#pragma unroll
            for (t = 0; t < 2; ++t) {
#pragma unroll
                for (j = 0; j < 4; ++j) {
                    mma16816(acc[t][j], ah[t][0], ah[t][1], ah[t][2], ah[t][3], bh[j][0], bh[j][1]);
                    mma16816(acc[t][j], ah[t][0], ah[t][1], ah[t][2], ah[t][3], bl[j][0], bl[j][1]);
                    mma16816(acc[t][j], al[t][0], al[t][1], al[t][2], al[t][3], bh[j][0], bh[j][1]);
                }
            }
        }

        __syncthreads();
        if (it + STAGES < NITER2) {
            stsA(smem, s, tid, a0, a1);
            load_stage_B(smem, s, it + STAGES, tid, kbase, Bhi, Blo);
        } else {
            __pipeline_commit();
        }
    }

    // epilogue: write fp32 partials (no ReLU here; combine kernel applies it)
    float* dst = &g_P[kh][0];

    const int g = lane >> 2;
    const int tig = lane & 3;
#pragma unroll
    for (t = 0; t < 2; ++t) {
#pragma unroll
        for (j = 0; j < 4; ++j) {
            int col = wn * 32 + j * 8 + tig * 2;
            size_t row0 = arow0 + wm * 32 + t * 16 + g;
            size_t row1 = row0 + 8;
            float2 v0;
            float2 v1;
            v0.x = acc[t][j][0];
            v0.y = acc[t][j][1];
            v1.x = acc[t][j][2];
            v1.y = acc[t][j][3];
            *reinterpret_cast<float2*>(dst + row0 * CD + col) = v0;
            *reinterpret_cast<float2*>(dst + row1 * CD + col) = v1;
        }
    }
}

extern "C" void kernel_launch(void* const* d_in, const int* in_sizes, int n_in,
                              void* d_out, int out_size)
{
    const float* A = (const float*)d_in[0];
    const float* F = (const float*)d_in[1];
    const float* G = (const float*)d_in[2];
    float* out = (float*)d_out;

    cudaFuncSetAttribute(gemm_kernel, cudaFuncAttributeMaxDynamicSharedMemorySize, SMEM_TOTAL);

    dim3 grid(NN / 64, 2);
    packX_kernel<<<(CD * NN) / 256, 256>>>(F, G);
    gemm_kernel<<<grid, 256, SMEM_TOTAL>>>(A, 0);
    combine0_kernel<<<(CD * NN) / 256, 256>>>();
    gemm_kernel<<<grid, 256, SMEM_TOTAL>>>(A, 1);
    combine1_kernel<<<(NN * CD) / 256, 256>>>(out);
}

// round 16
// speedup vs baseline: 2.7246x; 1.0426x over previous
#include <cuda_runtime.h>
#include <cuda_pipeline.h>
#include <cuda_bf16.h>

#define NN 8192
#define CD 128

#define BK 32
#define STAGES 3
#define STAGE_B 24576
#define OFF_ALO 4096
#define OFF_BHI 8192
#define OFF_BLO 16384
#define SMEM_TOTAL (STAGES * STAGE_B)
#define KSPLIT 3

__device__ __nv_bfloat16 g_Bhi[2][(size_t)CD * NN];
__device__ __nv_bfloat16 g_Blo[2][(size_t)CD * NN];
__device__ float g_P[KSPLIT][(size_t)NN * CD];

__device__ __forceinline__ void ldsm4(unsigned& r0, unsigned& r1, unsigned& r2, unsigned& r3, unsigned addr) {
    asm volatile("ldmatrix.sync.aligned.m8n8.x4.shared.b16 {%0, %1, %2, %3}, [%4];"
                 : "=r"(r0), "=r"(r1), "=r"(r2), "=r"(r3) : "r"(addr));
}
__device__ __forceinline__ void mma16816(float* c, unsigned a0, unsigned a1, unsigned a2, unsigned a3, unsigned b0, unsigned b1) {
    asm volatile("mma.sync.aligned.m16n8k16.row.col.f32.bf16.bf16.f32 {%0, %1, %2, %3}, {%4, %5, %6, %7}, {%8, %9}, {%0, %1, %2, %3};"
                 : "+f"(c[0]), "+f"(c[1]), "+f"(c[2]), "+f"(c[3])
                 : "r"(a0), "r"(a1), "r"(a2), "r"(a3), "r"(b0), "r"(b1));
}

__device__ __forceinline__ unsigned sw_off(int row, int chunk) {
    return (unsigned)(row * 64 + (chunk ^ ((row >> 1) & 3)) * 16);
}

__device__ __forceinline__ void split_bf16(float v, __nv_bfloat16& h, __nv_bfloat16& l) {
    h = __float2bfloat16_rn(v);
    l = __float2bfloat16_rn(v - __bfloat162float(h));
}
__device__ __forceinline__ unsigned pack_bf2(__nv_bfloat16 a, __nv_bfloat16 b) {
    unsigned lo = (unsigned)__bfloat16_as_ushort(a);
    unsigned hi = (unsigned)__bfloat16_as_ushort(b);
    return lo | (hi << 16);
}

__global__ __launch_bounds__(256) void packX_kernel(const float* __restrict__ F,
                                                    const float* __restrict__ G)
{
    int idx = blockIdx.x * blockDim.x + threadIdx.x;
    int col = idx >> 13;
    int row = idx & (NN - 1);
    float v;
    if (col < 64) v = F[row * 64 + col];
    else v = G[row * 64 + (col - 64)];
    __nv_bfloat16 h, l;
    split_bf16(v, h, l);
    g_Bhi[0][idx] = h;
    g_Blo[0][idx] = l;
}

// combine layer-1 partials -> ReLU(cols<64) -> layer-2 B operand (K-major limbs)
__global__ __launch_bounds__(256) void combine0_kernel()
{
    int idx = blockIdx.x * blockDim.x + threadIdx.x;   // idx = col*NN + row
    int col = idx >> 13;
    int row = idx & (NN - 1);
    size_t p = (size_t)row * CD + col;
    float v = g_P[0][p] + g_P[1][p] + g_P[2][p];
    if (col < 64) v = fmaxf(v, 0.0f);
    __nv_bfloat16 h, l;
    split_bf16(v, h, l);
    g_Bhi[1][idx] = h;
    g_Blo[1][idx] = l;
}

// combine layer-2 partials -> ReLU(cols<64) -> final output
__global__ __launch_bounds__(256) void combine1_kernel(float* __restrict__ out)
{
    int idx = blockIdx.x * blockDim.x + threadIdx.x;   // row-major over NN*CD
    int col = idx & (CD - 1);
    float v = g_P[0][idx] + g_P[1][idx] + g_P[2][idx];
    if (col < 64) v = fmaxf(v, 0.0f);
    out[idx] = v;
}

__device__ __forceinline__ void ldgA(const float* __restrict__ A, int it, int tid,
                                     size_t arow0, size_t kbase,
                                     float4& a0, float4& a1)
{
    int arow = tid >> 2;
    int achunk = tid & 3;
    size_t off = (arow0 + arow) * NN + kbase + (size_t)it * BK + achunk * 8;
    const float4* p = (const float4*)(A + off);
    a0 = p[0];
    a1 = p[1];
}

__device__ __forceinline__ void stsA(char* smem, int s, int tid, float4 a0, float4 a1)
{
    char* st = smem + s * STAGE_B;
    int arow = tid >> 2;
    int achunk = tid & 3;
    unsigned aso = sw_off(arow, achunk);
    __nv_bfloat16 h0, h1, h2, h3, h4, h5, h6, h7;
    __nv_bfloat16 l0, l1, l2, l3, l4, l5, l6, l7;
    split_bf16(a0.x, h0, l0);
    split_bf16(a0.y, h1, l1);
    split_bf16(a0.z, h2, l2);
    split_bf16(a0.w, h3, l3);
    split_bf16(a1.x, h4, l4);
    split_bf16(a1.y, h5, l5);
    split_bf16(a1.z, h6, l6);
    split_bf16(a1.w, h7, l7);
    uint4 wh;
    wh.x = pack_bf2(h0, h1);
    wh.y = pack_bf2(h2, h3);
    wh.z = pack_bf2(h4, h5);
    wh.w = pack_bf2(h6, h7);
    uint4 wl;
    wl.x = pack_bf2(l0, l1);
    wl.y = pack_bf2(l2, l3);
    wl.z = pack_bf2(l4, l5);
    wl.w = pack_bf2(l6, l7);
    *reinterpret_cast<uint4*>(st + aso) = wh;
    *reinterpret_cast<uint4*>(st + OFF_ALO + aso) = wl;
}

__device__ __forceinline__ void load_stage_B(char* smem, int s, int it, int tid, size_t kbase,
                                             const __nv_bfloat16* __restrict__ Bhi,
                                             const __nv_bfloat16* __restrict__ Blo)
{
    char* st = smem + s * STAGE_B;
    size_t k0 = kbase + (size_t)it * BK;
    int i;
#pragma unroll
    for (i = 0; i < 2; ++i) {
        int u = tid + i * 256;
        int brow = u >> 2;
        int bchunk = u & 3;
        unsigned bso = sw_off(brow, bchunk);
        size_t boff = (size_t)brow * NN + k0 + bchunk * 8;
        __pipeline_memcpy_async(st + OFF_BHI + bso, Bhi + boff, 16);
        __pipeline_memcpy_async(st + OFF_BLO + bso, Blo + boff, 16);
    }
    __pipeline_commit();
}

__global__ __launch_bounds__(256, 3) void gemm_kernel(const float* __restrict__ A, int layer)
{
    extern __shared__ char smem[];
    const int tid = threadIdx.x;
    const int lane = tid & 31;
    const int warp = tid >> 5;
    const int wm = warp & 1;
    const int wn = warp >> 1;
    const int kh = blockIdx.y;

    unsigned sbase = (unsigned)__cvta_generic_to_shared(smem);

    const __nv_bfloat16* Bhi = g_Bhi[layer];
    const __nv_bfloat16* Blo = g_Blo[layer];

    const size_t arow0 = (size_t)blockIdx.x * 64;
    // K split: 2688 / 2752 / 2752 (all multiples of BK)
    size_t kbase = 0;
    int niter = 84;
    if (kh == 1) { kbase = 2688; niter = 86; }
    if (kh == 2) { kbase = 5440; niter = 86; }

    float acc[2][4][4];
    int t, j, q;
#pragma unroll
    for (t = 0; t < 2; ++t)
#pragma unroll
        for (j = 0; j < 4; ++j)
#pragma unroll
            for (q = 0; q < 4; ++q) acc[t][j][q] = 0.0f;

    // prologue: fill all 3 stages
    {
        float4 p0[STAGES];
        float4 p1[STAGES];
        int c;
#pragma unroll
        for (c = 0; c < STAGES; ++c) ldgA(A, c, tid, arow0, kbase, p0[c], p1[c]);
#pragma unroll
        for (c = 0; c < STAGES; ++c) stsA(smem, c, tid, p0[c], p1[c]);
#pragma unroll
        for (c = 0; c < STAGES; ++c) load_stage_B(smem, c, c, tid, kbase, Bhi, Blo);
    }

    const int a_roff = lane & 15;
    const int a_coff = lane >> 4;
    const int b_m = lane >> 3;
    const int b_roff = ((b_m >> 1) * 8) + (lane & 7);
    const int b_coff = b_m & 1;

    int s = 0;
    for (int it = 0; it < niter; ++it) {
        __pipeline_wait_prior(STAGES - 1);
        __syncthreads();

        float4 a0, a1;
        if (it + STAGES < niter) ldgA(A, it + STAGES, tid, arow0, kbase, a0, a1);

        unsigned stb = sbase + s * STAGE_B;
        int ks;
#pragma unroll
        for (ks = 0; ks < 2; ++ks) {
            unsigned ah[2][4];
            unsigned al[2][4];
#pragma unroll
            for (t = 0; t < 2; ++t) {
                int row = wm * 32 + t * 16 + a_roff;
                int chunk = ks * 2 + a_coff;
                unsigned so = sw_off(row, chunk);
                ldsm4(ah[t][0], ah[t][1], ah[t][2], ah[t][3], stb + so);
                ldsm4(al[t][0], al[t][1], al[t][2], al[t][3], stb + OFF_ALO + so);
            }
            // process B two j-columns at a time to cut live registers
            int p;
#pragma unroll
            for (p = 0; p < 2; ++p) {
                int row = wn * 32 + p * 16 + b_roff;
                int chunk = ks * 2 + b_coff;
                unsigned so = sw_off(row, chunk);
                unsigned bh0, bh1, bh2, bh3;
                unsigned bl0, bl1, bl2, bl3;
                ldsm4(bh0, bh1, bh2, bh3, stb + OFF_BHI + so);
                ldsm4(bl0, bl1, bl2, bl3, stb + OFF_BLO + so);
                int j0 = p * 2;
#pragma unroll
                for (t = 0; t < 2; ++t) {
                    mma16816(acc[t][j0],     ah[t][0], ah[t][1], ah[t][2], ah[t][3], bh0, bh1);
                    mma16816(acc[t][j0],     ah[t][0], ah[t][1], ah[t][2], ah[t][3], bl0, bl1);
                    mma16816(acc[t][j0],     al[t][0], al[t][1], al[t][2], al[t][3], bh0, bh1);
                    mma16816(acc[t][j0 + 1], ah[t][0], ah[t][1], ah[t][2], ah[t][3], bh2, bh3);
                    mma16816(acc[t][j0 + 1], ah[t][0], ah[t][1], ah[t][2], ah[t][3], bl2, bl3);
                    mma16816(acc[t][j0 + 1], al[t][0], al[t][1], al[t][2], al[t][3], bh2, bh3);
                }
            }
        }

        __syncthreads();
        if (it + STAGES < niter) {
            stsA(smem, s, tid, a0, a1);
            load_stage_B(smem, s, it + STAGES, tid, kbase, Bhi, Blo);
        } else {
            __pipeline_commit();
        }
        ++s;
        if (s == STAGES) s = 0;
    }

    // epilogue: fp32 partials (combine kernel applies ReLU)
    float* dst = &g_P[kh][0];

    const int g = lane >> 2;
    const int tig = lane & 3;
#pragma unroll
    for (t = 0; t < 2; ++t) {
#pragma unroll
        for (j = 0; j < 4; ++j) {
            int col = wn * 32 + j * 8 + tig * 2;
            size_t row0 = arow0 + wm * 32 + t * 16 + g;
            size_t row1 = row0 + 8;
            float2 v0;
            float2 v1;
            v0.x = acc[t][j][0];
            v0.y = acc[t][j][1];
            v1.x = acc[t][j][2];
            v1.y = acc[t][j][3];
            *reinterpret_cast<float2*>(dst + row0 * CD + col) = v0;
            *reinterpret_cast<float2*>(dst + row1 * CD + col) = v1;
        }
    }
}

extern "C" void kernel_launch(void* const* d_in, const int* in_sizes, int n_in,
                              void* d_out, int out_size)
{
    const float* A = (const float*)d_in[0];
    const float* F = (const float*)d_in[1];
    const float* G = (const float*)d_in[2];
    float* out = (float*)d_out;

    cudaFuncSetAttribute(gemm_kernel, cudaFuncAttributeMaxDynamicSharedMemorySize, SMEM_TOTAL);

    dim3 grid(NN / 64, KSPLIT);
    packX_kernel<<<(CD * NN) / 256, 256>>>(F, G);
    gemm_kernel<<<grid, 256, SMEM_TOTAL>>>(A, 0);
    combine0_kernel<<<(CD * NN) / 256, 256>>>();
    gemm_kernel<<<grid, 256, SMEM_TOTAL>>>(A, 1);
    combine1_kernel<<<(NN * CD) / 256, 256>>>(out);
}